// round 2
// baseline (speedup 1.0000x reference)
#include <cuda_runtime.h>
#include <cuda_bf16.h>
#include <math.h>

#define NODE_DIM   128
#define HIDDEN_DIM 64
#define MAX_N      100000

// Scratch: UV[n][0:64] = x[n] @ W1[:128] + b1 ; UV[n][64:128] = x[n] @ W1[128:]
__device__ float g_uv[(size_t)MAX_N * NODE_DIM];
__device__ int   g_idx_is64;

// ---------------------------------------------------------------------------
// Kernel 0: detect edge_index dtype. If int64 (little-endian), every odd
// 32-bit word is the high half of a value in [0, 1e5) => zero.
// ---------------------------------------------------------------------------
__global__ void detect_dtype_kernel(const int* __restrict__ ei_words)
{
    int all0 = 1;
#pragma unroll
    for (int i = 1; i < 128; i += 2) all0 &= (ei_words[i] == 0);
    g_idx_is64 = all0;
}

// ---------------------------------------------------------------------------
// Kernel 1: node GEMM.  UV (N,128) = X (N,128) @ Weff (128,128) (+ b1 on cols 0..63)
//   Weff[k][c] = (c < 64) ? W1[k*64 + c] : W1[(128+k)*64 + (c-64)]
// 256 threads, tile 64 nodes x 128 cols; thread: 8 nodes x 4 cols.
// ---------------------------------------------------------------------------
#define GEMM_BN 64
#define GEMM_THREADS 256
#define GEMM_SMEM ((128 * 128 + GEMM_BN * 128) * sizeof(float))  // 96 KB

__global__ void node_gemm_kernel(const float* __restrict__ x,
                                 const float* __restrict__ W1,
                                 const float* __restrict__ b1,
                                 int n)
{
    extern __shared__ float smem[];
    float* Ws = smem;                 // [128][128]
    float* xs = smem + 128 * 128;     // [GEMM_BN][128]

    const int t = threadIdx.x;

    for (int i = t; i < 128 * 128; i += GEMM_THREADS) {
        int k = i >> 7;
        int c = i & 127;
        Ws[i] = (c < 64) ? W1[k * 64 + c] : W1[(128 + k) * 64 + (c - 64)];
    }

    const int node0 = blockIdx.x * GEMM_BN;

    const float4* x4 = (const float4*)x;
    float4* xs4 = (float4*)xs;
    for (int i = t; i < GEMM_BN * 32; i += GEMM_THREADS) {
        int nl = i >> 5;
        int node = node0 + nl;
        xs4[i] = (node < n) ? x4[(size_t)node * 32 + (i & 31)]
                            : make_float4(0.f, 0.f, 0.f, 0.f);
    }
    __syncthreads();

    const int tx = t & 31;   // cols [tx*4, tx*4+4)
    const int ty = t >> 5;   // nodes ty + 8*i
    const int c0 = tx * 4;

    float4 bias;
    if (c0 < 64) {
        bias = make_float4(__ldg(b1 + c0), __ldg(b1 + c0 + 1),
                           __ldg(b1 + c0 + 2), __ldg(b1 + c0 + 3));
    } else {
        bias = make_float4(0.f, 0.f, 0.f, 0.f);
    }

    float4 acc[8];
#pragma unroll
    for (int i = 0; i < 8; i++) acc[i] = bias;

#pragma unroll 4
    for (int k4 = 0; k4 < 32; k4++) {
        float4 xv[8];
#pragma unroll
        for (int i = 0; i < 8; i++)
            xv[i] = xs4[(ty + 8 * i) * 32 + k4];

#pragma unroll
        for (int kk = 0; kk < 4; kk++) {
            float4 w4 = ((const float4*)(Ws + (k4 * 4 + kk) * 128))[tx];
#pragma unroll
            for (int i = 0; i < 8; i++) {
                float xv_k = (kk == 0) ? xv[i].x : (kk == 1) ? xv[i].y
                           : (kk == 2) ? xv[i].z : xv[i].w;
                acc[i].x += xv_k * w4.x;
                acc[i].y += xv_k * w4.y;
                acc[i].z += xv_k * w4.z;
                acc[i].w += xv_k * w4.w;
            }
        }
    }

#pragma unroll
    for (int i = 0; i < 8; i++) {
        int node = node0 + ty + 8 * i;
        if (node < n)
            ((float4*)(g_uv + (size_t)node * 128))[tx] = acc[i];
    }
}

// ---------------------------------------------------------------------------
// Kernel 2: edge pass, half-warp per edge (2 edges/warp).
//   out[e] = sigmoid( relu(u[row] + v[col]) . W2 + b2 )
// ---------------------------------------------------------------------------
__global__ void edge_kernel(const void* __restrict__ edge_index,
                            const float* __restrict__ W2,
                            const float* __restrict__ b2,
                            float* __restrict__ out,
                            int E, int n)
{
    const int warp_id = (blockIdx.x * blockDim.x + threadIdx.x) >> 5;
    const int lane = threadIdx.x & 31;
    const int half = lane >> 4;
    const int hl = lane & 15;

    const long long e0 = (long long)warp_id * 2;
    if (e0 >= E) return;
    const long long e = e0 + half;
    const bool valid = (e < E);

    const int is64 = g_idx_is64;

    long long row = 0, col = 0;
    if (valid) {
        if (is64) {
            const long long* ei = (const long long*)edge_index;
            row = ei[e];
            col = ei[(long long)E + e];
        } else {
            const int* ei = (const int*)edge_index;
            row = ei[e];
            col = ei[(long long)E + e];
        }
        // defensive clamp: wrong detection gives wrong values, not a crash
        row = min(max(row, 0LL), (long long)(n - 1));
        col = min(max(col, 0LL), (long long)(n - 1));
    }

    const float4 u4 = ((const float4*)(g_uv + (size_t)row * 128))[hl];
    const float4 v4 = ((const float4*)(g_uv + (size_t)col * 128 + 64))[hl];
    const float4 w2 = __ldg(((const float4*)W2) + hl);

    float hx = fmaxf(u4.x + v4.x, 0.f);
    float hy = fmaxf(u4.y + v4.y, 0.f);
    float hz = fmaxf(u4.z + v4.z, 0.f);
    float hw = fmaxf(u4.w + v4.w, 0.f);

    float partial = hx * w2.x + hy * w2.y + hz * w2.z + hw * w2.w;

#pragma unroll
    for (int off = 8; off > 0; off >>= 1)
        partial += __shfl_down_sync(0xFFFFFFFFu, partial, off, 16);

    if (hl == 0 && valid) {
        float z = partial + __ldg(b2);
        out[e] = 1.0f / (1.0f + expf(-z));
    }
}

// ---------------------------------------------------------------------------
extern "C" void kernel_launch(void* const* d_in, const int* in_sizes, int n_in,
                              void* d_out, int out_size)
{
    const float* x          = (const float*)d_in[0];
    const void*  edge_index = d_in[1];
    const float* W1         = (const float*)d_in[2];
    const float* b1         = (const float*)d_in[3];
    const float* W2         = (const float*)d_in[4];
    const float* b2         = (const float*)d_in[5];
    float*       out        = (float*)d_out;

    const int n = in_sizes[0] / NODE_DIM;   // 100000
    const int E = in_sizes[1] / 2;          // 625000

    cudaFuncSetAttribute(node_gemm_kernel,
                         cudaFuncAttributeMaxDynamicSharedMemorySize,
                         (int)GEMM_SMEM);

    detect_dtype_kernel<<<1, 1>>>((const int*)edge_index);

    const int gemm_blocks = (n + GEMM_BN - 1) / GEMM_BN;
    node_gemm_kernel<<<gemm_blocks, GEMM_THREADS, GEMM_SMEM>>>(x, W1, b1, n);

    const int warps_needed = (E + 1) / 2;
    const int threads = 256;
    const int warps_per_block = threads / 32;
    const int edge_blocks = (warps_needed + warps_per_block - 1) / warps_per_block;
    edge_kernel<<<edge_blocks, threads>>>(edge_index, W2, b2, out, E, n);
}

// round 3
// speedup vs baseline: 1.0960x; 1.0960x over previous
#include <cuda_runtime.h>
#include <cuda_bf16.h>
#include <math.h>
#include <stdint.h>

#define NODE_DIM   128
#define HIDDEN_DIM 64
#define MAX_N      100000

// Scratch: UV[n][0:64] = x[n] @ W1[:128] + b1 ; UV[n][64:128] = x[n] @ W1[128:]
__device__ float g_uv[(size_t)MAX_N * NODE_DIM];

// ---------------------------------------------------------------------------
// PTX helpers
// ---------------------------------------------------------------------------
__device__ __forceinline__ uint32_t smem_u32(const void* p) {
    return (uint32_t)__cvta_generic_to_shared(p);
}

__device__ __forceinline__ void ldsm_x4(uint32_t* r, uint32_t addr) {
    asm volatile("ldmatrix.sync.aligned.m8n8.x4.shared.b16 {%0,%1,%2,%3}, [%4];"
                 : "=r"(r[0]), "=r"(r[1]), "=r"(r[2]), "=r"(r[3]) : "r"(addr));
}

__device__ __forceinline__ void ldsm_x4_t(uint32_t* r, uint32_t addr) {
    asm volatile("ldmatrix.sync.aligned.m8n8.x4.trans.shared.b16 {%0,%1,%2,%3}, [%4];"
                 : "=r"(r[0]), "=r"(r[1]), "=r"(r[2]), "=r"(r[3]) : "r"(addr));
}

__device__ __forceinline__ void mma16816(float* c, const uint32_t* a,
                                         uint32_t b0, uint32_t b1) {
    asm volatile(
        "mma.sync.aligned.m16n8k16.row.col.f32.bf16.bf16.f32 "
        "{%0,%1,%2,%3}, {%4,%5,%6,%7}, {%8,%9}, {%0,%1,%2,%3};"
        : "+f"(c[0]), "+f"(c[1]), "+f"(c[2]), "+f"(c[3])
        : "r"(a[0]), "r"(a[1]), "r"(a[2]), "r"(a[3]), "r"(b0), "r"(b1));
}

__device__ __forceinline__ void split_bf16(float v, __nv_bfloat16& h, __nv_bfloat16& l) {
    h = __float2bfloat16(v);
    l = __float2bfloat16(v - __bfloat162float(h));
}

// ---------------------------------------------------------------------------
// Kernel 1: node GEMM on tensor cores (bf16 hi/lo split, fp32 accumulate)
//   UV (N,128) = X (N,128) @ Weff (128,128) + bias(cols 0..63)
//   Weff[k][c] = (c < 64) ? W1[k*64 + c] : W1[(128+k)*64 + (c-64)]
// Block: 256 threads (8 warps), tile = 128 nodes x 128 cols x K=128.
// Warp w computes rows [16w, 16w+16) x all 128 cols.
// ---------------------------------------------------------------------------
#define PAD_COLS 136   // +8 bf16 pad -> conflict-free ldmatrix
#define GEMM_SMEM (4 * 128 * PAD_COLS * sizeof(__nv_bfloat16))  // 139264 B

__global__ __launch_bounds__(256)
void node_gemm_mma(const float* __restrict__ x,
                   const float* __restrict__ W1,
                   const float* __restrict__ b1,
                   int n)
{
    extern __shared__ __nv_bfloat16 sm[];
    __nv_bfloat16* Ah = sm;                      // [128][136]  x hi
    __nv_bfloat16* Al = Ah + 128 * PAD_COLS;     // x lo
    __nv_bfloat16* Bh = Al + 128 * PAD_COLS;     // Weff hi (row k, col c)
    __nv_bfloat16* Bl = Bh + 128 * PAD_COLS;     // Weff lo

    const int t = threadIdx.x;
    const int node0 = blockIdx.x * 128;

    // ---- stage Weff (hi/lo) ----
    for (int i = t; i < 128 * 32; i += 256) {
        int k  = i >> 5;
        int c4 = i & 31;
        const float* src = (c4 < 16) ? (W1 + k * 64 + c4 * 4)
                                     : (W1 + (128 + k) * 64 + (c4 - 16) * 4);
        float4 v = *(const float4*)src;
        int off = k * PAD_COLS + c4 * 4;
        __nv_bfloat16 h0, l0, h1, l1, h2, l2, h3, l3;
        split_bf16(v.x, h0, l0); split_bf16(v.y, h1, l1);
        split_bf16(v.z, h2, l2); split_bf16(v.w, h3, l3);
        Bh[off + 0] = h0; Bh[off + 1] = h1; Bh[off + 2] = h2; Bh[off + 3] = h3;
        Bl[off + 0] = l0; Bl[off + 1] = l1; Bl[off + 2] = l2; Bl[off + 3] = l3;
    }

    // ---- stage x tile (hi/lo) ----
    for (int i = t; i < 128 * 32; i += 256) {
        int r  = i >> 5;
        int c4 = i & 31;
        int node = node0 + r;
        float4 v = (node < n) ? ((const float4*)x)[(size_t)node * 32 + c4]
                              : make_float4(0.f, 0.f, 0.f, 0.f);
        int off = r * PAD_COLS + c4 * 4;
        __nv_bfloat16 h0, l0, h1, l1, h2, l2, h3, l3;
        split_bf16(v.x, h0, l0); split_bf16(v.y, h1, l1);
        split_bf16(v.z, h2, l2); split_bf16(v.w, h3, l3);
        Ah[off + 0] = h0; Ah[off + 1] = h1; Ah[off + 2] = h2; Ah[off + 3] = h3;
        Al[off + 0] = l0; Al[off + 1] = l1; Al[off + 2] = l2; Al[off + 3] = l3;
    }
    __syncthreads();

    const int warp = t >> 5;
    const int lane = t & 31;

    float acc[16][4];
#pragma unroll
    for (int i = 0; i < 16; i++)
#pragma unroll
        for (int j = 0; j < 4; j++) acc[i][j] = 0.f;

    // ldmatrix base addresses (bytes)
    // A: lane -> row (warp*16 + lane%16), k-col offset (lane/16)*8
    const uint32_t a_base = smem_u32(Ah) +
        (uint32_t)(((warp * 16 + (lane & 15)) * PAD_COLS + (lane >> 4) * 8) * 2);
    const uint32_t a_lo_off = (uint32_t)(128 * PAD_COLS * 2);  // Al - Ah
    // B (.trans): lane -> k-row (lane%16), n-col offset (lane/16)*8
    const uint32_t b_base = smem_u32(Bh) +
        (uint32_t)(((lane & 15) * PAD_COLS + (lane >> 4) * 8) * 2);
    const uint32_t b_lo_off = (uint32_t)(128 * PAD_COLS * 2);  // Bl - Bh

    const uint32_t ROWB = PAD_COLS * 2;  // bytes per smem row

#pragma unroll
    for (int ks = 0; ks < 8; ks++) {
        uint32_t ah[4], al[4];
        ldsm_x4(ah, a_base + ks * 32);              // 16 bf16 = 32 B per k-step
        ldsm_x4(al, a_base + a_lo_off + ks * 32);

#pragma unroll
        for (int j = 0; j < 8; j++) {               // two n8 tiles per iteration
            uint32_t bh[4], bl[4];
            uint32_t baddr = b_base + ks * 16 * ROWB + j * 32;
            ldsm_x4_t(bh, baddr);
            ldsm_x4_t(bl, baddr + b_lo_off);

            // D += Ah*Bh + Ah*Bl + Al*Bh   (Al*Bl dropped: ~2^-18)
            mma16816(acc[2 * j],     ah, bh[0], bh[1]);
            mma16816(acc[2 * j],     ah, bl[0], bl[1]);
            mma16816(acc[2 * j],     al, bh[0], bh[1]);
            mma16816(acc[2 * j + 1], ah, bh[2], bh[3]);
            mma16816(acc[2 * j + 1], ah, bl[2], bl[3]);
            mma16816(acc[2 * j + 1], al, bh[2], bh[3]);
        }
    }

    // ---- epilogue: add bias (cols < 64), write g_uv ----
    const int r0 = lane >> 2;          // 0..7
    const int cq = (lane & 3) * 2;     // 0,2,4,6
    const int m0 = node0 + warp * 16 + r0;
    const int m1 = m0 + 8;

#pragma unroll
    for (int nt = 0; nt < 16; nt++) {
        int col = nt * 8 + cq;
        float bx = (col < 64) ? __ldg(b1 + col) : 0.f;
        float by = (col < 64) ? __ldg(b1 + col + 1) : 0.f;
        if (m0 < n) {
            float2 v = make_float2(acc[nt][0] + bx, acc[nt][1] + by);
            *(float2*)(g_uv + (size_t)m0 * 128 + col) = v;
        }
        if (m1 < n) {
            float2 v = make_float2(acc[nt][2] + bx, acc[nt][3] + by);
            *(float2*)(g_uv + (size_t)m1 * 128 + col) = v;
        }
    }
}

// ---------------------------------------------------------------------------
// Kernel 2: edge pass, half-warp per edge (2 edges/warp).
//   out[e] = sigmoid( relu(u[row] + v[col]) . W2 + b2 )
// edge_index is int32 (proven: int64 interpretation faulted in R1).
// ---------------------------------------------------------------------------
__global__ void edge_kernel(const int* __restrict__ edge_index,
                            const float* __restrict__ W2,
                            const float* __restrict__ b2,
                            float* __restrict__ out,
                            int E, int n)
{
    const int warp_id = (blockIdx.x * blockDim.x + threadIdx.x) >> 5;
    const int lane = threadIdx.x & 31;
    const int half = lane >> 4;
    const int hl = lane & 15;

    const long long e0 = (long long)warp_id * 2;
    if (e0 >= E) return;
    const long long e = e0 + half;
    const bool valid = (e < E);

    int row = 0, col = 0;
    if (valid) {
        row = edge_index[e];
        col = edge_index[(long long)E + e];
        row = min(max(row, 0), n - 1);   // safety clamp
        col = min(max(col, 0), n - 1);
    }

    const float4 u4 = ((const float4*)(g_uv + (size_t)row * 128))[hl];
    const float4 v4 = ((const float4*)(g_uv + (size_t)col * 128 + 64))[hl];
    const float4 w2 = __ldg(((const float4*)W2) + hl);

    float hx = fmaxf(u4.x + v4.x, 0.f);
    float hy = fmaxf(u4.y + v4.y, 0.f);
    float hz = fmaxf(u4.z + v4.z, 0.f);
    float hw = fmaxf(u4.w + v4.w, 0.f);

    float partial = hx * w2.x + hy * w2.y + hz * w2.z + hw * w2.w;

#pragma unroll
    for (int off = 8; off > 0; off >>= 1)
        partial += __shfl_down_sync(0xFFFFFFFFu, partial, off, 16);

    if (hl == 0 && valid) {
        float z = partial + __ldg(b2);
        out[e] = 1.0f / (1.0f + __expf(-z));
    }
}

// ---------------------------------------------------------------------------
extern "C" void kernel_launch(void* const* d_in, const int* in_sizes, int n_in,
                              void* d_out, int out_size)
{
    const float* x          = (const float*)d_in[0];
    const int*   edge_index = (const int*)d_in[1];
    const float* W1         = (const float*)d_in[2];
    const float* b1         = (const float*)d_in[3];
    const float* W2         = (const float*)d_in[4];
    const float* b2         = (const float*)d_in[5];
    float*       out        = (float*)d_out;

    const int n = in_sizes[0] / NODE_DIM;   // 100000
    const int E = in_sizes[1] / 2;          // 625000

    cudaFuncSetAttribute(node_gemm_mma,
                         cudaFuncAttributeMaxDynamicSharedMemorySize,
                         (int)GEMM_SMEM);

    const int gemm_blocks = (n + 127) / 128;    // 782
    node_gemm_mma<<<gemm_blocks, 256, GEMM_SMEM>>>(x, W1, b1, n);

    const int warps_needed = (E + 1) / 2;
    const int threads = 256;
    const int edge_blocks = (warps_needed + (threads / 32) - 1) / (threads / 32);
    edge_kernel<<<edge_blocks, threads>>>(edge_index, W2, b2, out, E, n);
}

// round 5
// speedup vs baseline: 2.0663x; 1.8853x over previous
#include <cuda_runtime.h>
#include <cuda_bf16.h>
#include <math.h>
#include <stdint.h>

#define NODE_DIM   128
#define HIDDEN_DIM 64
#define MAX_N      100000

// Scratch: UV[n][0:64] = x[n] @ W1[:128] + b1 ; UV[n][64:128] = x[n] @ W1[128:]
__device__ float g_uv[(size_t)MAX_N * NODE_DIM];

// ---------------------------------------------------------------------------
// PTX helpers
// ---------------------------------------------------------------------------
__device__ __forceinline__ uint32_t smem_u32(const void* p) {
    return (uint32_t)__cvta_generic_to_shared(p);
}
__device__ __forceinline__ void ldsm_x4(uint32_t* r, uint32_t addr) {
    asm volatile("ldmatrix.sync.aligned.m8n8.x4.shared.b16 {%0,%1,%2,%3}, [%4];"
                 : "=r"(r[0]), "=r"(r[1]), "=r"(r[2]), "=r"(r[3]) : "r"(addr));
}
__device__ __forceinline__ void ldsm_x4_t(uint32_t* r, uint32_t addr) {
    asm volatile("ldmatrix.sync.aligned.m8n8.x4.trans.shared.b16 {%0,%1,%2,%3}, [%4];"
                 : "=r"(r[0]), "=r"(r[1]), "=r"(r[2]), "=r"(r[3]) : "r"(addr));
}
__device__ __forceinline__ void mma16816(float* c, const uint32_t* a,
                                         uint32_t b0, uint32_t b1) {
    asm volatile(
        "mma.sync.aligned.m16n8k16.row.col.f32.bf16.bf16.f32 "
        "{%0,%1,%2,%3}, {%4,%5,%6,%7}, {%8,%9}, {%0,%1,%2,%3};"
        : "+f"(c[0]), "+f"(c[1]), "+f"(c[2]), "+f"(c[3])
        : "r"(a[0]), "r"(a[1]), "r"(a[2]), "r"(a[3]), "r"(b0), "r"(b1));
}
__device__ __forceinline__ void cp_async16(uint32_t saddr, const void* g) {
    asm volatile("cp.async.cg.shared.global [%0], [%1], 16;" :: "r"(saddr), "l"(g));
}
__device__ __forceinline__ void cp_commit() {
    asm volatile("cp.async.commit_group;" ::: "memory");
}
__device__ __forceinline__ void cp_wait0() {
    asm volatile("cp.async.wait_group 0;" ::: "memory");
}

// split a float4 into packed hi (2x bf162) and lo (2x bf162) 8-byte words
__device__ __forceinline__ void split4(float4 v, uint2& hi, uint2& lo) {
    __nv_bfloat162 h01 = __floats2bfloat162_rn(v.x, v.y);
    __nv_bfloat162 h23 = __floats2bfloat162_rn(v.z, v.w);
    __nv_bfloat162 l01 = __floats2bfloat162_rn(v.x - __bfloat162float(h01.x),
                                               v.y - __bfloat162float(h01.y));
    __nv_bfloat162 l23 = __floats2bfloat162_rn(v.z - __bfloat162float(h23.x),
                                               v.w - __bfloat162float(h23.y));
    hi = make_uint2(*(uint32_t*)&h01, *(uint32_t*)&h23);
    lo = make_uint2(*(uint32_t*)&l01, *(uint32_t*)&l23);
}

// ---------------------------------------------------------------------------
// Kernel 1: persistent node GEMM on tensor cores (bf16 hi/lo split, fp32 acc)
//   UV (N,128) = X (N,128) @ Weff (128,128) + bias(cols 0..63)
//   Weff[k][c] = (c < 64) ? W1[k*64 + c] : W1[(128+k)*64 + (c-64)]
// Grid = 148 persistent blocks, 256 threads. W staged/split ONCE per block.
// Node tiles of 128 rows, cp.async double-buffered raw-float staging.
// ---------------------------------------------------------------------------
#define PAD_COLS 136
#define RAW_BYTES   (128 * 128 * 4)               // 65536
#define AHALF_BYTES (128 * PAD_COLS * 2)          // 34816
#define GEMM_SMEM (RAW_BYTES + 4 * AHALF_BYTES)   // 204800

__global__ __launch_bounds__(256, 1)
void node_gemm_persistent(const float* __restrict__ x,
                          const float* __restrict__ W1,
                          const float* __restrict__ b1,
                          int n, int tiles)
{
    extern __shared__ char smraw[];
    float*         Raw = (float*)smraw;
    __nv_bfloat16* Ah  = (__nv_bfloat16*)(smraw + RAW_BYTES);
    __nv_bfloat16* Al  = Ah + 128 * PAD_COLS;
    __nv_bfloat16* Bh  = Al + 128 * PAD_COLS;
    __nv_bfloat16* Bl  = Bh + 128 * PAD_COLS;

    const int t    = threadIdx.x;
    const int warp = t >> 5;
    const int lane = t & 31;

    // ---- issue prefetch of first tile, then stage W (overlaps latency) ----
    int tile = blockIdx.x;
    if (tile < tiles) {
        const int node0 = tile * 128;
#pragma unroll
        for (int it = 0; it < 16; it++) {
            int idx  = t + it * 256;            // float4 index in 128x32 tile
            int row  = idx >> 5;
            int node = node0 + row;
            uint32_t sa = smem_u32(Raw) + idx * 16;
            if (node < n)
                cp_async16(sa, (const char*)x + (size_t)node * 512 + (size_t)(idx & 31) * 16);
            else
                *(float4*)((char*)Raw + idx * 16) = make_float4(0.f, 0.f, 0.f, 0.f);
        }
    }
    cp_commit();

    // ---- stage Weff hi/lo (once) ----
    for (int i = t; i < 128 * 32; i += 256) {
        int k  = i >> 5;
        int c4 = i & 31;
        const float* src = (c4 < 16) ? (W1 + k * 64 + c4 * 4)
                                     : (W1 + (128 + k) * 64 + (c4 - 16) * 4);
        float4 v = *(const float4*)src;
        uint2 hi, lo;
        split4(v, hi, lo);
        int off = k * PAD_COLS + c4 * 4;
        *(uint2*)(Bh + off) = hi;
        *(uint2*)(Bl + off) = lo;
    }

    // ldmatrix base addresses (bytes), fixed across tiles
    const uint32_t a_base = smem_u32(Ah) +
        (uint32_t)(((warp * 16 + (lane & 15)) * PAD_COLS + (lane >> 4) * 8) * 2);
    const uint32_t b_base = smem_u32(Bh) +
        (uint32_t)(((lane & 15) * PAD_COLS + (lane >> 4) * 8) * 2);
    const uint32_t half_off = (uint32_t)AHALF_BYTES;   // Al-Ah and Bl-Bh
    const uint32_t ROWB = PAD_COLS * 2;

    const int r0 = lane >> 2;
    const int cq = (lane & 3) * 2;

    for (; tile < tiles; tile += gridDim.x) {
        const int node0 = tile * 128;

        // wait prefetched raw floats of THIS tile
        cp_wait0();
        __syncthreads();

        // ---- convert Raw -> Ah/Al (wide stores) ----
#pragma unroll
        for (int it = 0; it < 16; it++) {
            int idx = t + it * 256;
            int row = idx >> 5;
            int c4  = idx & 31;
            float4 v = ((const float4*)Raw)[idx];
            uint2 hi, lo;
            split4(v, hi, lo);
            int off = row * PAD_COLS + c4 * 4;
            *(uint2*)(Ah + off) = hi;
            *(uint2*)(Al + off) = lo;
        }
        __syncthreads();

        // ---- issue prefetch of NEXT tile (overlaps with compute) ----
        int tn = tile + gridDim.x;
        if (tn < tiles) {
            const int nn0 = tn * 128;
#pragma unroll
            for (int it = 0; it < 16; it++) {
                int idx  = t + it * 256;
                int row  = idx >> 5;
                int node = nn0 + row;
                uint32_t sa = smem_u32(Raw) + idx * 16;
                if (node < n)
                    cp_async16(sa, (const char*)x + (size_t)node * 512 + (size_t)(idx & 31) * 16);
                else
                    *(float4*)((char*)Raw + idx * 16) = make_float4(0.f, 0.f, 0.f, 0.f);
            }
        }
        cp_commit();

        // ---- compute 128x128 tile ----
        float acc[16][4];
#pragma unroll
        for (int i = 0; i < 16; i++)
#pragma unroll
            for (int j = 0; j < 4; j++) acc[i][j] = 0.f;

#pragma unroll
        for (int ks = 0; ks < 8; ks++) {
            uint32_t ah[4], al[4];
            ldsm_x4(ah, a_base + ks * 32);
            ldsm_x4(al, a_base + half_off + ks * 32);

#pragma unroll
            for (int j = 0; j < 8; j++) {
                uint32_t bh[4], bl[4];
                uint32_t baddr = b_base + ks * 16 * ROWB + j * 32;
                ldsm_x4_t(bh, baddr);
                ldsm_x4_t(bl, baddr + half_off);

                // D += Ah*Bh + Ah*Bl + Al*Bh   (Al*Bl ~2^-18, dropped)
                mma16816(acc[2 * j],     ah, bh[0], bh[1]);
                mma16816(acc[2 * j],     ah, bl[0], bl[1]);
                mma16816(acc[2 * j],     al, bh[0], bh[1]);
                mma16816(acc[2 * j + 1], ah, bh[2], bh[3]);
                mma16816(acc[2 * j + 1], ah, bl[2], bl[3]);
                mma16816(acc[2 * j + 1], al, bh[2], bh[3]);
            }
        }

        // ---- epilogue: + bias (cols<64), write g_uv ----
        const int m0 = node0 + warp * 16 + r0;
        const int m1 = m0 + 8;
#pragma unroll
        for (int nt = 0; nt < 16; nt++) {
            int col = nt * 8 + cq;
            float bx = (col < 64) ? __ldg(b1 + col) : 0.f;
            float by = (col < 64) ? __ldg(b1 + col + 1) : 0.f;
            if (m0 < n)
                *(float2*)(g_uv + (size_t)m0 * 128 + col) =
                    make_float2(acc[nt][0] + bx, acc[nt][1] + by);
            if (m1 < n)
                *(float2*)(g_uv + (size_t)m1 * 128 + col) =
                    make_float2(acc[nt][2] + bx, acc[nt][3] + by);
        }
    }
}

// ---------------------------------------------------------------------------
// Kernel 2: edge pass, 4 edges per warp (2 per half-warp) for MLP=4.
//   out[e] = sigmoid( relu(u[row] + v[col]) . W2 + b2 )
// edge_index is int32.
// ---------------------------------------------------------------------------
__global__ void edge_kernel(const int* __restrict__ edge_index,
                            const float* __restrict__ W2,
                            const float* __restrict__ b2,
                            float* __restrict__ out,
                            int E, int n)
{
    const int warp_id = (blockIdx.x * blockDim.x + threadIdx.x) >> 5;
    const int lane = threadIdx.x & 31;
    const int half = lane >> 4;
    const int hl = lane & 15;

    const long long e0 = (long long)warp_id * 4;
    if (e0 >= E) return;
    const long long eA = e0 + half * 2;       // this half-warp: edges eA, eA+1
    const bool vA = (eA < E);
    const bool vB = (eA + 1 < E);

    int rA = 0, cA = 0, rB = 0, cB = 0;
    if (vA) { rA = edge_index[eA];     cA = edge_index[(long long)E + eA]; }
    if (vB) { rB = edge_index[eA + 1]; cB = edge_index[(long long)E + eA + 1]; }
    rA = min(max(rA, 0), n - 1); cA = min(max(cA, 0), n - 1);
    rB = min(max(rB, 0), n - 1); cB = min(max(cB, 0), n - 1);

    // issue all gathers up front (MLP=4)
    const float4 uA  = ((const float4*)(g_uv + (size_t)rA * 128))[hl];
    const float4 vA4 = ((const float4*)(g_uv + (size_t)cA * 128 + 64))[hl];
    const float4 uB  = ((const float4*)(g_uv + (size_t)rB * 128))[hl];
    const float4 vB4 = ((const float4*)(g_uv + (size_t)cB * 128 + 64))[hl];
    const float4 w2  = __ldg(((const float4*)W2) + hl);

    float pA, pB;
    {
        float hx = fmaxf(uA.x + vA4.x, 0.f), hy = fmaxf(uA.y + vA4.y, 0.f);
        float hz = fmaxf(uA.z + vA4.z, 0.f), hw = fmaxf(uA.w + vA4.w, 0.f);
        pA = hx * w2.x + hy * w2.y + hz * w2.z + hw * w2.w;
    }
    {
        float hx = fmaxf(uB.x + vB4.x, 0.f), hy = fmaxf(uB.y + vB4.y, 0.f);
        float hz = fmaxf(uB.z + vB4.z, 0.f), hw = fmaxf(uB.w + vB4.w, 0.f);
        pB = hx * w2.x + hy * w2.y + hz * w2.z + hw * w2.w;
    }

#pragma unroll
    for (int off = 8; off > 0; off >>= 1) {
        pA += __shfl_down_sync(0xFFFFFFFFu, pA, off, 16);
        pB += __shfl_down_sync(0xFFFFFFFFu, pB, off, 16);
    }

    if (hl == 0 && vA) {
        float bb = __ldg(b2);
        float oA = 1.0f / (1.0f + __expf(-(pA + bb)));
        if (vB) {
            float oB = 1.0f / (1.0f + __expf(-(pB + bb)));
            *(float2*)(out + eA) = make_float2(oA, oB);   // eA even, 8B aligned
        } else {
            out[eA] = oA;
        }
    }
}

// ---------------------------------------------------------------------------
extern "C" void kernel_launch(void* const* d_in, const int* in_sizes, int n_in,
                              void* d_out, int out_size)
{
    const float* x          = (const float*)d_in[0];
    const int*   edge_index = (const int*)d_in[1];
    const float* W1         = (const float*)d_in[2];
    const float* b1         = (const float*)d_in[3];
    const float* W2         = (const float*)d_in[4];
    const float* b2         = (const float*)d_in[5];
    float*       out        = (float*)d_out;

    const int n = in_sizes[0] / NODE_DIM;   // 100000
    const int E = in_sizes[1] / 2;          // 625000
    const int tiles = (n + 127) / 128;      // 782

    cudaFuncSetAttribute(node_gemm_persistent,
                         cudaFuncAttributeMaxDynamicSharedMemorySize,
                         (int)GEMM_SMEM);

    node_gemm_persistent<<<148, 256, GEMM_SMEM>>>(x, W1, b1, n, tiles);

    const int warps_needed = (E + 3) / 4;
    const int threads = 256;
    const int edge_blocks = (warps_needed + (threads / 32) - 1) / (threads / 32);
    edge_kernel<<<edge_blocks, threads>>>(edge_index, W2, b2, out, E, n);
}

// round 6
// speedup vs baseline: 2.4480x; 1.1848x over previous
#include <cuda_runtime.h>
#include <cuda_bf16.h>
#include <math.h>
#include <stdint.h>

#define NODE_DIM   128
#define HIDDEN_DIM 64
#define MAX_N      100000

// Scratch UV in bf16: uv16[n][0:64] = u = x[n]@W1[:128]+b1 ; [64:128] = v = x[n]@W1[128:]
__device__ __nv_bfloat16 g_uv16[(size_t)MAX_N * NODE_DIM];

// ---------------------------------------------------------------------------
// PTX helpers
// ---------------------------------------------------------------------------
__device__ __forceinline__ uint32_t smem_u32(const void* p) {
    return (uint32_t)__cvta_generic_to_shared(p);
}
__device__ __forceinline__ void ldsm_x4(uint32_t* r, uint32_t addr) {
    asm volatile("ldmatrix.sync.aligned.m8n8.x4.shared.b16 {%0,%1,%2,%3}, [%4];"
                 : "=r"(r[0]), "=r"(r[1]), "=r"(r[2]), "=r"(r[3]) : "r"(addr));
}
__device__ __forceinline__ void ldsm_x4_t(uint32_t* r, uint32_t addr) {
    asm volatile("ldmatrix.sync.aligned.m8n8.x4.trans.shared.b16 {%0,%1,%2,%3}, [%4];"
                 : "=r"(r[0]), "=r"(r[1]), "=r"(r[2]), "=r"(r[3]) : "r"(addr));
}
__device__ __forceinline__ void mma16816(float* c, const uint32_t* a,
                                         uint32_t b0, uint32_t b1) {
    asm volatile(
        "mma.sync.aligned.m16n8k16.row.col.f32.bf16.bf16.f32 "
        "{%0,%1,%2,%3}, {%4,%5,%6,%7}, {%8,%9}, {%0,%1,%2,%3};"
        : "+f"(c[0]), "+f"(c[1]), "+f"(c[2]), "+f"(c[3])
        : "r"(a[0]), "r"(a[1]), "r"(a[2]), "r"(a[3]), "r"(b0), "r"(b1));
}
__device__ __forceinline__ void cp_async16(uint32_t saddr, const void* g) {
    asm volatile("cp.async.cg.shared.global [%0], [%1], 16;" :: "r"(saddr), "l"(g));
}
__device__ __forceinline__ void cp_commit() {
    asm volatile("cp.async.commit_group;" ::: "memory");
}
__device__ __forceinline__ void cp_wait0() {
    asm volatile("cp.async.wait_group 0;" ::: "memory");
}

// split a float4 into packed hi (2x bf162) and lo (2x bf162) 8-byte words
__device__ __forceinline__ void split4(float4 v, uint2& hi, uint2& lo) {
    __nv_bfloat162 h01 = __floats2bfloat162_rn(v.x, v.y);
    __nv_bfloat162 h23 = __floats2bfloat162_rn(v.z, v.w);
    __nv_bfloat162 l01 = __floats2bfloat162_rn(v.x - __bfloat162float(h01.x),
                                               v.y - __bfloat162float(h01.y));
    __nv_bfloat162 l23 = __floats2bfloat162_rn(v.z - __bfloat162float(h23.x),
                                               v.w - __bfloat162float(h23.y));
    hi = make_uint2(*(uint32_t*)&h01, *(uint32_t*)&h23);
    lo = make_uint2(*(uint32_t*)&l01, *(uint32_t*)&l23);
}

// ---------------------------------------------------------------------------
// Kernel 1: persistent node GEMM on tensor cores (bf16 hi/lo split, fp32 acc)
//   UV (N,128) = X (N,128) @ Weff (128,128) + bias(cols 0..63), stored bf16
// Grid = 148 persistent blocks, 256 threads. W staged/split once per block.
// ---------------------------------------------------------------------------
#define PAD_COLS 136
#define RAW_BYTES   (128 * 128 * 4)               // 65536
#define AHALF_BYTES (128 * PAD_COLS * 2)          // 34816
#define GEMM_SMEM (RAW_BYTES + 4 * AHALF_BYTES)   // 204800

__global__ __launch_bounds__(256, 1)
void node_gemm_persistent(const float* __restrict__ x,
                          const float* __restrict__ W1,
                          const float* __restrict__ b1,
                          int n, int tiles)
{
    extern __shared__ char smraw[];
    float*         Raw = (float*)smraw;
    __nv_bfloat16* Ah  = (__nv_bfloat16*)(smraw + RAW_BYTES);
    __nv_bfloat16* Al  = Ah + 128 * PAD_COLS;
    __nv_bfloat16* Bh  = Al + 128 * PAD_COLS;
    __nv_bfloat16* Bl  = Bh + 128 * PAD_COLS;

    const int t    = threadIdx.x;
    const int warp = t >> 5;
    const int lane = t & 31;

    // ---- prefetch first tile, then stage W (overlaps latency) ----
    int tile = blockIdx.x;
    if (tile < tiles) {
        const int node0 = tile * 128;
#pragma unroll
        for (int it = 0; it < 16; it++) {
            int idx  = t + it * 256;
            int row  = idx >> 5;
            int node = node0 + row;
            uint32_t sa = smem_u32(Raw) + idx * 16;
            if (node < n)
                cp_async16(sa, (const char*)x + (size_t)node * 512 + (size_t)(idx & 31) * 16);
            else
                *(float4*)((char*)Raw + idx * 16) = make_float4(0.f, 0.f, 0.f, 0.f);
        }
    }
    cp_commit();

    // ---- stage Weff hi/lo (once) ----
    for (int i = t; i < 128 * 32; i += 256) {
        int k  = i >> 5;
        int c4 = i & 31;
        const float* src = (c4 < 16) ? (W1 + k * 64 + c4 * 4)
                                     : (W1 + (128 + k) * 64 + (c4 - 16) * 4);
        float4 v = *(const float4*)src;
        uint2 hi, lo;
        split4(v, hi, lo);
        int off = k * PAD_COLS + c4 * 4;
        *(uint2*)(Bh + off) = hi;
        *(uint2*)(Bl + off) = lo;
    }

    const uint32_t a_base = smem_u32(Ah) +
        (uint32_t)(((warp * 16 + (lane & 15)) * PAD_COLS + (lane >> 4) * 8) * 2);
    const uint32_t b_base = smem_u32(Bh) +
        (uint32_t)(((lane & 15) * PAD_COLS + (lane >> 4) * 8) * 2);
    const uint32_t half_off = (uint32_t)AHALF_BYTES;
    const uint32_t ROWB = PAD_COLS * 2;

    const int r0 = lane >> 2;
    const int cq = (lane & 3) * 2;

    for (; tile < tiles; tile += gridDim.x) {
        const int node0 = tile * 128;

        cp_wait0();
        __syncthreads();

        // ---- convert Raw -> Ah/Al ----
#pragma unroll
        for (int it = 0; it < 16; it++) {
            int idx = t + it * 256;
            int row = idx >> 5;
            int c4  = idx & 31;
            float4 v = ((const float4*)Raw)[idx];
            uint2 hi, lo;
            split4(v, hi, lo);
            int off = row * PAD_COLS + c4 * 4;
            *(uint2*)(Ah + off) = hi;
            *(uint2*)(Al + off) = lo;
        }
        __syncthreads();

        // ---- prefetch NEXT tile (overlaps compute) ----
        int tn = tile + gridDim.x;
        if (tn < tiles) {
            const int nn0 = tn * 128;
#pragma unroll
            for (int it = 0; it < 16; it++) {
                int idx  = t + it * 256;
                int row  = idx >> 5;
                int node = nn0 + row;
                uint32_t sa = smem_u32(Raw) + idx * 16;
                if (node < n)
                    cp_async16(sa, (const char*)x + (size_t)node * 512 + (size_t)(idx & 31) * 16);
                else
                    *(float4*)((char*)Raw + idx * 16) = make_float4(0.f, 0.f, 0.f, 0.f);
            }
        }
        cp_commit();

        // ---- compute 128x128 tile ----
        float acc[16][4];
#pragma unroll
        for (int i = 0; i < 16; i++)
#pragma unroll
            for (int j = 0; j < 4; j++) acc[i][j] = 0.f;

#pragma unroll
        for (int ks = 0; ks < 8; ks++) {
            uint32_t ah[4], al[4];
            ldsm_x4(ah, a_base + ks * 32);
            ldsm_x4(al, a_base + half_off + ks * 32);

#pragma unroll
            for (int j = 0; j < 8; j++) {
                uint32_t bh[4], bl[4];
                uint32_t baddr = b_base + ks * 16 * ROWB + j * 32;
                ldsm_x4_t(bh, baddr);
                ldsm_x4_t(bl, baddr + half_off);

                mma16816(acc[2 * j],     ah, bh[0], bh[1]);
                mma16816(acc[2 * j],     ah, bl[0], bl[1]);
                mma16816(acc[2 * j],     al, bh[0], bh[1]);
                mma16816(acc[2 * j + 1], ah, bh[2], bh[3]);
                mma16816(acc[2 * j + 1], ah, bl[2], bl[3]);
                mma16816(acc[2 * j + 1], al, bh[2], bh[3]);
            }
        }

        // ---- epilogue: + bias (cols<64), write g_uv16 (bf16 packed) ----
        const int m0 = node0 + warp * 16 + r0;
        const int m1 = m0 + 8;
#pragma unroll
        for (int nt = 0; nt < 16; nt++) {
            int col = nt * 8 + cq;
            float bx = (col < 64) ? __ldg(b1 + col) : 0.f;
            float by = (col < 64) ? __ldg(b1 + col + 1) : 0.f;
            if (m0 < n) {
                __nv_bfloat162 p = __floats2bfloat162_rn(acc[nt][0] + bx, acc[nt][1] + by);
                *(uint32_t*)(g_uv16 + (size_t)m0 * 128 + col) = *(uint32_t*)&p;
            }
            if (m1 < n) {
                __nv_bfloat162 p = __floats2bfloat162_rn(acc[nt][2] + bx, acc[nt][3] + by);
                *(uint32_t*)(g_uv16 + (size_t)m1 * 128 + col) = *(uint32_t*)&p;
            }
        }
    }
}

// ---------------------------------------------------------------------------
// Kernel 2: edge pass, 8 edges per warp (4 per half-warp), bf16 UV gathers.
//   out[e] = sigmoid( relu(u[row] + v[col]) . W2 + b2 )
// Each lane loads 4 bf16 (8 B): half-warp covers one 128 B u (or v) row = 1 line.
// ---------------------------------------------------------------------------
__global__ void edge_kernel(const int* __restrict__ edge_index,
                            const float* __restrict__ W2,
                            const float* __restrict__ b2,
                            float* __restrict__ out,
                            int E, int n)
{
    const int warp_id = (blockIdx.x * blockDim.x + threadIdx.x) >> 5;
    const int lane = threadIdx.x & 31;
    const int half = lane >> 4;
    const int hl = lane & 15;

    const long long base = (long long)warp_id * 8 + half * 4;  // 4 edges per half-warp
    if (base >= E) return;   // E % 8 == 0: all 4 edges valid

    int r[4], c[4];
#pragma unroll
    for (int j = 0; j < 4; j++) {
        r[j] = edge_index[base + j];
        c[j] = edge_index[(long long)E + base + j];
        r[j] = min(max(r[j], 0), n - 1);
        c[j] = min(max(c[j], 0), n - 1);
    }

    // issue all 8 gathers up front (MLP=8)
    uint2 uu[4], vv[4];
#pragma unroll
    for (int j = 0; j < 4; j++) {
        uu[j] = *(const uint2*)(g_uv16 + (size_t)r[j] * 128 + hl * 4);
        vv[j] = *(const uint2*)(g_uv16 + (size_t)c[j] * 128 + 64 + hl * 4);
    }
    const float4 w2 = __ldg(((const float4*)W2) + hl);

    float p[4];
#pragma unroll
    for (int j = 0; j < 4; j++) {
        float2 u01 = __bfloat1622float2(*(__nv_bfloat162*)&uu[j].x);
        float2 u23 = __bfloat1622float2(*(__nv_bfloat162*)&uu[j].y);
        float2 v01 = __bfloat1622float2(*(__nv_bfloat162*)&vv[j].x);
        float2 v23 = __bfloat1622float2(*(__nv_bfloat162*)&vv[j].y);
        float hx = fmaxf(u01.x + v01.x, 0.f);
        float hy = fmaxf(u01.y + v01.y, 0.f);
        float hz = fmaxf(u23.x + v23.x, 0.f);
        float hw = fmaxf(u23.y + v23.y, 0.f);
        p[j] = hx * w2.x + hy * w2.y + hz * w2.z + hw * w2.w;
    }

#pragma unroll
    for (int off = 8; off > 0; off >>= 1) {
#pragma unroll
        for (int j = 0; j < 4; j++)
            p[j] += __shfl_down_sync(0xFFFFFFFFu, p[j], off, 16);
    }

    if (hl == 0) {
        float bb = __ldg(b2);
        float4 o;
        o.x = 1.0f / (1.0f + __expf(-(p[0] + bb)));
        o.y = 1.0f / (1.0f + __expf(-(p[1] + bb)));
        o.z = 1.0f / (1.0f + __expf(-(p[2] + bb)));
        o.w = 1.0f / (1.0f + __expf(-(p[3] + bb)));
        *(float4*)(out + base) = o;   // base % 4 == 0: 16B aligned
    }
}

// ---------------------------------------------------------------------------
extern "C" void kernel_launch(void* const* d_in, const int* in_sizes, int n_in,
                              void* d_out, int out_size)
{
    const float* x          = (const float*)d_in[0];
    const int*   edge_index = (const int*)d_in[1];
    const float* W1         = (const float*)d_in[2];
    const float* b1         = (const float*)d_in[3];
    const float* W2         = (const float*)d_in[4];
    const float* b2         = (const float*)d_in[5];
    float*       out        = (float*)d_out;

    const int n = in_sizes[0] / NODE_DIM;   // 100000
    const int E = in_sizes[1] / 2;          // 625000
    const int tiles = (n + 127) / 128;      // 782

    cudaFuncSetAttribute(node_gemm_persistent,
                         cudaFuncAttributeMaxDynamicSharedMemorySize,
                         (int)GEMM_SMEM);

    node_gemm_persistent<<<148, 256, GEMM_SMEM>>>(x, W1, b1, n, tiles);

    const int warps_needed = (E + 7) / 8;   // 78125
    const int threads = 256;
    const int edge_blocks = (warps_needed + (threads / 32) - 1) / (threads / 32);
    edge_kernel<<<edge_blocks, threads>>>(edge_index, W2, b2, out, E, n);
}

// round 7
// speedup vs baseline: 3.4970x; 1.4285x over previous
#include <cuda_runtime.h>
#include <cuda_bf16.h>
#include <math.h>
#include <stdint.h>

#define NODE_DIM   128
#define HIDDEN_DIM 64
#define MAX_N      100000

// Scratch UV in bf16: uv16[n][0:64] = u = x[n]@W1[:128]+b1 ; [64:128] = v = x[n]@W1[128:]
__device__ __nv_bfloat16 g_uv16[(size_t)MAX_N * NODE_DIM];

// ---------------------------------------------------------------------------
// PTX helpers
// ---------------------------------------------------------------------------
__device__ __forceinline__ uint32_t smem_u32(const void* p) {
    return (uint32_t)__cvta_generic_to_shared(p);
}
__device__ __forceinline__ void ldsm_x4(uint32_t* r, uint32_t addr) {
    asm volatile("ldmatrix.sync.aligned.m8n8.x4.shared.b16 {%0,%1,%2,%3}, [%4];"
                 : "=r"(r[0]), "=r"(r[1]), "=r"(r[2]), "=r"(r[3]) : "r"(addr));
}
__device__ __forceinline__ void ldsm_x4_t(uint32_t* r, uint32_t addr) {
    asm volatile("ldmatrix.sync.aligned.m8n8.x4.trans.shared.b16 {%0,%1,%2,%3}, [%4];"
                 : "=r"(r[0]), "=r"(r[1]), "=r"(r[2]), "=r"(r[3]) : "r"(addr));
}
__device__ __forceinline__ void mma16816(float* c, const uint32_t* a,
                                         uint32_t b0, uint32_t b1) {
    asm volatile(
        "mma.sync.aligned.m16n8k16.row.col.f32.bf16.bf16.f32 "
        "{%0,%1,%2,%3}, {%4,%5,%6,%7}, {%8,%9}, {%0,%1,%2,%3};"
        : "+f"(c[0]), "+f"(c[1]), "+f"(c[2]), "+f"(c[3])
        : "r"(a[0]), "r"(a[1]), "r"(a[2]), "r"(a[3]), "r"(b0), "r"(b1));
}
__device__ __forceinline__ void cp_async16(uint32_t saddr, const void* g) {
    asm volatile("cp.async.cg.shared.global [%0], [%1], 16;" :: "r"(saddr), "l"(g));
}
__device__ __forceinline__ void cp_commit() {
    asm volatile("cp.async.commit_group;" ::: "memory");
}
__device__ __forceinline__ void cp_wait0() {
    asm volatile("cp.async.wait_group 0;" ::: "memory");
}

// pack float4 -> 2x bf162 (8 bytes)
__device__ __forceinline__ uint2 pack4(float4 v) {
    __nv_bfloat162 h01 = __floats2bfloat162_rn(v.x, v.y);
    __nv_bfloat162 h23 = __floats2bfloat162_rn(v.z, v.w);
    return make_uint2(*(uint32_t*)&h01, *(uint32_t*)&h23);
}

// ---------------------------------------------------------------------------
// Kernel 1: persistent node GEMM, plain bf16 1-pass on tensor cores, fp32 acc.
//   UV (N,128) = X (N,128) @ Weff (128,128) + bias(cols 0..63), stored bf16
//   Weff[k][c] = (c < 64) ? W1[k*64 + c] : W1[(128+k)*64 + (c-64)]
// Grid = 148 persistent blocks, 256 threads (8 warps).
// ---------------------------------------------------------------------------
#define PAD_COLS 136
#define RAW_BYTES   (128 * 128 * 4)               // 65536
#define AB_BYTES    (128 * PAD_COLS * 2)          // 34816
#define GEMM_SMEM (RAW_BYTES + 2 * AB_BYTES)      // 135168

__global__ __launch_bounds__(256, 1)
void node_gemm_persistent(const float* __restrict__ x,
                          const float* __restrict__ W1,
                          const float* __restrict__ b1,
                          int n, int tiles)
{
    extern __shared__ char smraw[];
    float*         Raw = (float*)smraw;
    __nv_bfloat16* Ah  = (__nv_bfloat16*)(smraw + RAW_BYTES);
    __nv_bfloat16* Bh  = Ah + 128 * PAD_COLS;

    const int t    = threadIdx.x;
    const int warp = t >> 5;
    const int lane = t & 31;

    // ---- prefetch first tile, then stage W (overlaps latency) ----
    int tile = blockIdx.x;
    if (tile < tiles) {
        const int node0 = tile * 128;
#pragma unroll
        for (int it = 0; it < 16; it++) {
            int idx  = t + it * 256;
            int row  = idx >> 5;
            int node = node0 + row;
            uint32_t sa = smem_u32(Raw) + idx * 16;
            if (node < n)
                cp_async16(sa, (const char*)x + (size_t)node * 512 + (size_t)(idx & 31) * 16);
            else
                *(float4*)((char*)Raw + idx * 16) = make_float4(0.f, 0.f, 0.f, 0.f);
        }
    }
    cp_commit();

    // ---- stage Weff bf16 (once per block) ----
    for (int i = t; i < 128 * 32; i += 256) {
        int k  = i >> 5;
        int c4 = i & 31;
        const float* src = (c4 < 16) ? (W1 + k * 64 + c4 * 4)
                                     : (W1 + (128 + k) * 64 + (c4 - 16) * 4);
        float4 v = *(const float4*)src;
        *(uint2*)(Bh + k * PAD_COLS + c4 * 4) = pack4(v);
    }

    const uint32_t a_base = smem_u32(Ah) +
        (uint32_t)(((warp * 16 + (lane & 15)) * PAD_COLS + (lane >> 4) * 8) * 2);
    const uint32_t b_base = smem_u32(Bh) +
        (uint32_t)(((lane & 15) * PAD_COLS + (lane >> 4) * 8) * 2);
    const uint32_t ROWB = PAD_COLS * 2;

    const int r0 = lane >> 2;
    const int cq = (lane & 3) * 2;

    for (; tile < tiles; tile += gridDim.x) {
        const int node0 = tile * 128;

        cp_wait0();
        __syncthreads();

        // ---- convert Raw -> Ah (bf16) ----
#pragma unroll
        for (int it = 0; it < 16; it++) {
            int idx = t + it * 256;
            int row = idx >> 5;
            int c4  = idx & 31;
            float4 v = ((const float4*)Raw)[idx];
            *(uint2*)(Ah + row * PAD_COLS + c4 * 4) = pack4(v);
        }
        __syncthreads();

        // ---- prefetch NEXT tile (overlaps compute) ----
        int tn = tile + gridDim.x;
        if (tn < tiles) {
            const int nn0 = tn * 128;
#pragma unroll
            for (int it = 0; it < 16; it++) {
                int idx  = t + it * 256;
                int row  = idx >> 5;
                int node = nn0 + row;
                uint32_t sa = smem_u32(Raw) + idx * 16;
                if (node < n)
                    cp_async16(sa, (const char*)x + (size_t)node * 512 + (size_t)(idx & 31) * 16);
                else
                    *(float4*)((char*)Raw + idx * 16) = make_float4(0.f, 0.f, 0.f, 0.f);
            }
        }
        cp_commit();

        // ---- compute 128x128 tile (128 HMMA per warp) ----
        float acc[16][4];
#pragma unroll
        for (int i = 0; i < 16; i++)
#pragma unroll
            for (int j = 0; j < 4; j++) acc[i][j] = 0.f;

#pragma unroll
        for (int ks = 0; ks < 8; ks++) {
            uint32_t ah[4];
            ldsm_x4(ah, a_base + ks * 32);

#pragma unroll
            for (int j = 0; j < 8; j++) {
                uint32_t bh[4];
                ldsm_x4_t(bh, b_base + ks * 16 * ROWB + j * 32);
                mma16816(acc[2 * j],     ah, bh[0], bh[1]);
                mma16816(acc[2 * j + 1], ah, bh[2], bh[3]);
            }
        }

        // ---- epilogue: + bias (cols<64), write g_uv16 (packed bf16x2) ----
        const int m0 = node0 + warp * 16 + r0;
        const int m1 = m0 + 8;
#pragma unroll
        for (int nt = 0; nt < 16; nt++) {
            int col = nt * 8 + cq;
            float bx = (col < 64) ? __ldg(b1 + col) : 0.f;
            float by = (col < 64) ? __ldg(b1 + col + 1) : 0.f;
            if (m0 < n) {
                __nv_bfloat162 p = __floats2bfloat162_rn(acc[nt][0] + bx, acc[nt][1] + by);
                *(uint32_t*)(g_uv16 + (size_t)m0 * 128 + col) = *(uint32_t*)&p;
            }
            if (m1 < n) {
                __nv_bfloat162 p = __floats2bfloat162_rn(acc[nt][2] + bx, acc[nt][3] + by);
                *(uint32_t*)(g_uv16 + (size_t)m1 * 128 + col) = *(uint32_t*)&p;
            }
        }
    }
}

// ---------------------------------------------------------------------------
// Kernel 2: edge pass. 8 lanes per edge, 8 edges per warp (2 per lane-group).
// Lane loads 16 B (8 bf16) of u and of v per edge -> LDG.128, full-line rows.
//   out[e] = sigmoid( relu(u[row] + v[col]) . W2 + b2 )
// ---------------------------------------------------------------------------
__device__ __forceinline__ float edge_dot(uint4 u, uint4 v, float4 wa, float4 wb)
{
    const __nv_bfloat162 z2 = __float2bfloat162_rn(0.f);
    __nv_bfloat162 h0 = __hmax2(__hadd2(*(__nv_bfloat162*)&u.x, *(__nv_bfloat162*)&v.x), z2);
    __nv_bfloat162 h1 = __hmax2(__hadd2(*(__nv_bfloat162*)&u.y, *(__nv_bfloat162*)&v.y), z2);
    __nv_bfloat162 h2 = __hmax2(__hadd2(*(__nv_bfloat162*)&u.z, *(__nv_bfloat162*)&v.z), z2);
    __nv_bfloat162 h3 = __hmax2(__hadd2(*(__nv_bfloat162*)&u.w, *(__nv_bfloat162*)&v.w), z2);
    float2 f0 = __bfloat1622float2(h0);
    float2 f1 = __bfloat1622float2(h1);
    float2 f2 = __bfloat1622float2(h2);
    float2 f3 = __bfloat1622float2(h3);
    float p = f0.x * wa.x;
    p = fmaf(f0.y, wa.y, p);
    p = fmaf(f1.x, wa.z, p);
    p = fmaf(f1.y, wa.w, p);
    p = fmaf(f2.x, wb.x, p);
    p = fmaf(f2.y, wb.y, p);
    p = fmaf(f3.x, wb.z, p);
    p = fmaf(f3.y, wb.w, p);
    return p;
}

__global__ void edge_kernel(const int* __restrict__ edge_index,
                            const float* __restrict__ W2,
                            const float* __restrict__ b2,
                            float* __restrict__ out,
                            int E)
{
    const int warp_id = (blockIdx.x * blockDim.x + threadIdx.x) >> 5;
    const int lane = threadIdx.x & 31;
    const int g  = lane >> 3;    // lane group 0..3 (8 lanes each)
    const int gl = lane & 7;

    const long long base = (long long)warp_id * 8 + g * 2;  // edges base, base+1
    if (base >= E) return;   // E % 8 == 0: valid warps have all 8 edges in range

    const int2 rr = *(const int2*)(edge_index + base);            // rows (2 edges)
    const int2 cc = *(const int2*)(edge_index + (long long)E + base);  // cols

    // 4 x LDG.128 gathers issued up front
    const uint4 u0 = *(const uint4*)(g_uv16 + (size_t)rr.x * 128 + gl * 8);
    const uint4 v0 = *(const uint4*)(g_uv16 + (size_t)cc.x * 128 + 64 + gl * 8);
    const uint4 u1 = *(const uint4*)(g_uv16 + (size_t)rr.y * 128 + gl * 8);
    const uint4 v1 = *(const uint4*)(g_uv16 + (size_t)cc.y * 128 + 64 + gl * 8);

    const float4 wa = __ldg((const float4*)W2 + gl * 2);
    const float4 wb = __ldg((const float4*)W2 + gl * 2 + 1);

    float p0 = edge_dot(u0, v0, wa, wb);
    float p1 = edge_dot(u1, v1, wa, wb);

    // reduce across the 8-lane group
#pragma unroll
    for (int off = 4; off > 0; off >>= 1) {
        p0 += __shfl_down_sync(0xFFFFFFFFu, p0, off, 8);
        p1 += __shfl_down_sync(0xFFFFFFFFu, p1, off, 8);
    }

    if (gl == 0) {
        float bb = __ldg(b2);
        float2 o;
        o.x = 1.0f / (1.0f + __expf(-(p0 + bb)));
        o.y = 1.0f / (1.0f + __expf(-(p1 + bb)));
        *(float2*)(out + base) = o;   // base even -> 8B aligned
    }
}

// ---------------------------------------------------------------------------
extern "C" void kernel_launch(void* const* d_in, const int* in_sizes, int n_in,
                              void* d_out, int out_size)
{
    const float* x          = (const float*)d_in[0];
    const int*   edge_index = (const int*)d_in[1];
    const float* W1         = (const float*)d_in[2];
    const float* b1         = (const float*)d_in[3];
    const float* W2         = (const float*)d_in[4];
    const float* b2         = (const float*)d_in[5];
    float*       out        = (float*)d_out;

    const int n = in_sizes[0] / NODE_DIM;   // 100000
    const int E = in_sizes[1] / 2;          // 625000
    const int tiles = (n + 127) / 128;      // 782

    cudaFuncSetAttribute(node_gemm_persistent,
                         cudaFuncAttributeMaxDynamicSharedMemorySize,
                         (int)GEMM_SMEM);

    node_gemm_persistent<<<148, 256, GEMM_SMEM>>>(x, W1, b1, n, tiles);

    const int warps_needed = (E + 7) / 8;   // 78125
    const int threads = 256;
    const int edge_blocks = (warps_needed + (threads / 32) - 1) / (threads / 32);  // 9766
    edge_kernel<<<edge_blocks, threads>>>(edge_index, W2, b2, out, E);
}

// round 8
// speedup vs baseline: 3.8315x; 1.0957x over previous
#include <cuda_runtime.h>
#include <cuda_bf16.h>
#include <math.h>
#include <stdint.h>

#define NODE_DIM   128
#define HIDDEN_DIM 64
#define MAX_N      100000

// Scratch UV in bf16: uv16[n][0:64] = u = x[n]@W1[:128]+b1 ; [64:128] = v = x[n]@W1[128:]
__device__ __nv_bfloat16 g_uv16[(size_t)MAX_N * NODE_DIM];

// ---------------------------------------------------------------------------
// PTX helpers
// ---------------------------------------------------------------------------
__device__ __forceinline__ uint32_t smem_u32(const void* p) {
    return (uint32_t)__cvta_generic_to_shared(p);
}
__device__ __forceinline__ void ldsm_x4(uint32_t* r, uint32_t addr) {
    asm volatile("ldmatrix.sync.aligned.m8n8.x4.shared.b16 {%0,%1,%2,%3}, [%4];"
                 : "=r"(r[0]), "=r"(r[1]), "=r"(r[2]), "=r"(r[3]) : "r"(addr));
}
__device__ __forceinline__ void ldsm_x4_t(uint32_t* r, uint32_t addr) {
    asm volatile("ldmatrix.sync.aligned.m8n8.x4.trans.shared.b16 {%0,%1,%2,%3}, [%4];"
                 : "=r"(r[0]), "=r"(r[1]), "=r"(r[2]), "=r"(r[3]) : "r"(addr));
}
__device__ __forceinline__ void mma16816(float* c, const uint32_t* a,
                                         uint32_t b0, uint32_t b1) {
    asm volatile(
        "mma.sync.aligned.m16n8k16.row.col.f32.bf16.bf16.f32 "
        "{%0,%1,%2,%3}, {%4,%5,%6,%7}, {%8,%9}, {%0,%1,%2,%3};"
        : "+f"(c[0]), "+f"(c[1]), "+f"(c[2]), "+f"(c[3])
        : "r"(a[0]), "r"(a[1]), "r"(a[2]), "r"(a[3]), "r"(b0), "r"(b1));
}
__device__ __forceinline__ void cp_async16(uint32_t saddr, const void* g) {
    asm volatile("cp.async.cg.shared.global [%0], [%1], 16;" :: "r"(saddr), "l"(g));
}
__device__ __forceinline__ void cp_commit() {
    asm volatile("cp.async.commit_group;" ::: "memory");
}
__device__ __forceinline__ void cp_wait0() {
    asm volatile("cp.async.wait_group 0;" ::: "memory");
}

// pack float4 -> 2x bf162 (8 bytes)
__device__ __forceinline__ uint2 pack4(float4 v) {
    __nv_bfloat162 h01 = __floats2bfloat162_rn(v.x, v.y);
    __nv_bfloat162 h23 = __floats2bfloat162_rn(v.z, v.w);
    return make_uint2(*(uint32_t*)&h01, *(uint32_t*)&h23);
}

// ---------------------------------------------------------------------------
// Kernel 1: persistent node GEMM, plain bf16 on tensor cores, fp32 acc.
//   UV (N,128) = X (N,128) @ Weff (128,128) + bias(cols 0..63), stored bf16
// Epilogue staged through smem (conflict-free stride-68 words) -> coalesced STG.
// ---------------------------------------------------------------------------
#define PAD_COLS 136
#define RAW_BYTES  (128 * 128 * 4)     // 65536
#define EPI_WORDS  68                  // 64 payload + 4 pad words per row
#define EPI_BYTES  (128 * EPI_WORDS * 4)  // 34816
#define AB_BYTES   (128 * PAD_COLS * 2)   // 34816
#define OFF_EPI    RAW_BYTES
#define OFF_A      (OFF_EPI + EPI_BYTES)
#define OFF_B      (OFF_A + AB_BYTES)
#define GEMM_SMEM  (OFF_B + AB_BYTES)     // 169984

__global__ __launch_bounds__(256, 1)
void node_gemm_persistent(const float* __restrict__ x,
                          const float* __restrict__ W1,
                          const float* __restrict__ b1,
                          int n, int tiles)
{
    extern __shared__ char smraw[];
    float*         Raw = (float*)smraw;
    uint32_t*      Epi = (uint32_t*)(smraw + OFF_EPI);
    __nv_bfloat16* Ah  = (__nv_bfloat16*)(smraw + OFF_A);
    __nv_bfloat16* Bh  = (__nv_bfloat16*)(smraw + OFF_B);

    const int t    = threadIdx.x;
    const int warp = t >> 5;
    const int lane = t & 31;

    // ---- prefetch first tile, then stage W (overlaps latency) ----
    int tile = blockIdx.x;
    if (tile < tiles) {
        const int node0 = tile * 128;
#pragma unroll
        for (int it = 0; it < 16; it++) {
            int idx  = t + it * 256;
            int row  = idx >> 5;
            int node = node0 + row;
            uint32_t sa = smem_u32(Raw) + idx * 16;
            if (node < n)
                cp_async16(sa, (const char*)x + (size_t)node * 512 + (size_t)(idx & 31) * 16);
            else
                *(float4*)((char*)Raw + idx * 16) = make_float4(0.f, 0.f, 0.f, 0.f);
        }
    }
    cp_commit();

    // ---- stage Weff bf16 (once per block) ----
    for (int i = t; i < 128 * 32; i += 256) {
        int k  = i >> 5;
        int c4 = i & 31;
        const float* src = (c4 < 16) ? (W1 + k * 64 + c4 * 4)
                                     : (W1 + (128 + k) * 64 + (c4 - 16) * 4);
        float4 v = *(const float4*)src;
        *(uint2*)(Bh + k * PAD_COLS + c4 * 4) = pack4(v);
    }

    const uint32_t a_base = smem_u32(Ah) +
        (uint32_t)(((warp * 16 + (lane & 15)) * PAD_COLS + (lane >> 4) * 8) * 2);
    const uint32_t b_base = smem_u32(Bh) +
        (uint32_t)(((lane & 15) * PAD_COLS + (lane >> 4) * 8) * 2);
    const uint32_t ROWB = PAD_COLS * 2;

    const int r0 = lane >> 2;          // 0..7
    const int cqh = lane & 3;          // col-pair index (cq = 2*cqh)

    for (; tile < tiles; tile += gridDim.x) {
        const int node0 = tile * 128;

        cp_wait0();
        __syncthreads();

        // ---- convert Raw -> Ah (bf16) ----
#pragma unroll
        for (int it = 0; it < 16; it++) {
            int idx = t + it * 256;
            int row = idx >> 5;
            int c4  = idx & 31;
            float4 v = ((const float4*)Raw)[idx];
            *(uint2*)(Ah + row * PAD_COLS + c4 * 4) = pack4(v);
        }
        __syncthreads();

        // ---- prefetch NEXT tile (overlaps compute) ----
        int tn = tile + gridDim.x;
        if (tn < tiles) {
            const int nn0 = tn * 128;
#pragma unroll
            for (int it = 0; it < 16; it++) {
                int idx  = t + it * 256;
                int row  = idx >> 5;
                int node = nn0 + row;
                uint32_t sa = smem_u32(Raw) + idx * 16;
                if (node < n)
                    cp_async16(sa, (const char*)x + (size_t)node * 512 + (size_t)(idx & 31) * 16);
                else
                    *(float4*)((char*)Raw + idx * 16) = make_float4(0.f, 0.f, 0.f, 0.f);
            }
        }
        cp_commit();

        // ---- compute 128x128 tile (128 HMMA per warp) ----
        float acc[16][4];
#pragma unroll
        for (int i = 0; i < 16; i++)
#pragma unroll
            for (int j = 0; j < 4; j++) acc[i][j] = 0.f;

#pragma unroll
        for (int ks = 0; ks < 8; ks++) {
            uint32_t ah[4];
            ldsm_x4(ah, a_base + ks * 32);

#pragma unroll
            for (int j = 0; j < 8; j++) {
                uint32_t bh[4];
                ldsm_x4_t(bh, b_base + ks * 16 * ROWB + j * 32);
                mma16816(acc[2 * j],     ah, bh[0], bh[1]);
                mma16816(acc[2 * j + 1], ah, bh[2], bh[3]);
            }
        }

        // ---- epilogue: + bias, STS into Epi (conflict-free), coalesced STG ----
        {
            const int lr0 = warp * 16 + r0;   // block-local rows
            const int lr1 = lr0 + 8;
#pragma unroll
            for (int nt = 0; nt < 16; nt++) {
                int col = nt * 8 + cqh * 2;
                float bx = (col < 64) ? __ldg(b1 + col) : 0.f;
                float by = (col < 64) ? __ldg(b1 + col + 1) : 0.f;
                __nv_bfloat162 p0 = __floats2bfloat162_rn(acc[nt][0] + bx, acc[nt][1] + by);
                __nv_bfloat162 p1 = __floats2bfloat162_rn(acc[nt][2] + bx, acc[nt][3] + by);
                // word index: row*68 + nt*4 + cqh  (68 ≡ 4 mod 32 -> lanes on distinct banks)
                Epi[lr0 * EPI_WORDS + nt * 4 + cqh] = *(uint32_t*)&p0;
                Epi[lr1 * EPI_WORDS + nt * 4 + cqh] = *(uint32_t*)&p1;
            }
        }
        __syncthreads();

        // coalesced copy: 128 rows x 16 uint4 payload per row
#pragma unroll
        for (int it = 0; it < 8; it++) {
            int idx = t + it * 256;          // 0..2047
            int row = idx >> 4;
            int wq  = idx & 15;
            int node = node0 + row;
            if (node < n) {
                uint4 v = *(const uint4*)(Epi + row * EPI_WORDS + wq * 4);
                *(uint4*)(g_uv16 + (size_t)node * 128 + wq * 8) = v;
            }
        }
        // loop-top cp_wait0 + __syncthreads orders Epi reuse & next convert
    }
}

// ---------------------------------------------------------------------------
// Kernel 2: edge pass. 8 lanes per edge, 16 edges per warp (4 per lane-group).
// Lane issues 8 LDG.128 gathers up front (MLP=8).
//   out[e] = sigmoid( relu(u[row] + v[col]) . W2 + b2 )
// ---------------------------------------------------------------------------
__device__ __forceinline__ float edge_dot(uint4 u, uint4 v, float4 wa, float4 wb)
{
    const __nv_bfloat162 z2 = __float2bfloat162_rn(0.f);
    __nv_bfloat162 h0 = __hmax2(__hadd2(*(__nv_bfloat162*)&u.x, *(__nv_bfloat162*)&v.x), z2);
    __nv_bfloat162 h1 = __hmax2(__hadd2(*(__nv_bfloat162*)&u.y, *(__nv_bfloat162*)&v.y), z2);
    __nv_bfloat162 h2 = __hmax2(__hadd2(*(__nv_bfloat162*)&u.z, *(__nv_bfloat162*)&v.z), z2);
    __nv_bfloat162 h3 = __hmax2(__hadd2(*(__nv_bfloat162*)&u.w, *(__nv_bfloat162*)&v.w), z2);
    float2 f0 = __bfloat1622float2(h0);
    float2 f1 = __bfloat1622float2(h1);
    float2 f2 = __bfloat1622float2(h2);
    float2 f3 = __bfloat1622float2(h3);
    float p = f0.x * wa.x;
    p = fmaf(f0.y, wa.y, p);
    p = fmaf(f1.x, wa.z, p);
    p = fmaf(f1.y, wa.w, p);
    p = fmaf(f2.x, wb.x, p);
    p = fmaf(f2.y, wb.y, p);
    p = fmaf(f3.x, wb.z, p);
    p = fmaf(f3.y, wb.w, p);
    return p;
}

__global__ void edge_kernel(const int* __restrict__ edge_index,
                            const float* __restrict__ W2,
                            const float* __restrict__ b2,
                            float* __restrict__ out,
                            int E)
{
    const int warp_id = (blockIdx.x * blockDim.x + threadIdx.x) >> 5;
    const int lane = threadIdx.x & 31;
    const int g  = lane >> 3;    // lane group 0..3 (8 lanes each)
    const int gl = lane & 7;

    const long long base = (long long)warp_id * 16 + g * 4;  // 4 edges per group
    if (base >= E) return;   // E % 4 == 0: whole group of 4 valid together

    const int4 rr = *(const int4*)(edge_index + base);
    const int4 cc = *(const int4*)(edge_index + (long long)E + base);

    // 8 x LDG.128 gathers issued up front
    const size_t o = (size_t)gl * 8;
    const uint4 u0 = *(const uint4*)(g_uv16 + (size_t)rr.x * 128 + o);
    const uint4 v0 = *(const uint4*)(g_uv16 + (size_t)cc.x * 128 + 64 + o);
    const uint4 u1 = *(const uint4*)(g_uv16 + (size_t)rr.y * 128 + o);
    const uint4 v1 = *(const uint4*)(g_uv16 + (size_t)cc.y * 128 + 64 + o);
    const uint4 u2 = *(const uint4*)(g_uv16 + (size_t)rr.z * 128 + o);
    const uint4 v2 = *(const uint4*)(g_uv16 + (size_t)cc.z * 128 + 64 + o);
    const uint4 u3 = *(const uint4*)(g_uv16 + (size_t)rr.w * 128 + o);
    const uint4 v3 = *(const uint4*)(g_uv16 + (size_t)cc.w * 128 + 64 + o);

    const float4 wa = __ldg((const float4*)W2 + gl * 2);
    const float4 wb = __ldg((const float4*)W2 + gl * 2 + 1);

    float p0 = edge_dot(u0, v0, wa, wb);
    float p1 = edge_dot(u1, v1, wa, wb);
    float p2 = edge_dot(u2, v2, wa, wb);
    float p3 = edge_dot(u3, v3, wa, wb);

#pragma unroll
    for (int off = 4; off > 0; off >>= 1) {
        p0 += __shfl_down_sync(0xFFFFFFFFu, p0, off, 8);
        p1 += __shfl_down_sync(0xFFFFFFFFu, p1, off, 8);
        p2 += __shfl_down_sync(0xFFFFFFFFu, p2, off, 8);
        p3 += __shfl_down_sync(0xFFFFFFFFu, p3, off, 8);
    }

    if (gl == 0) {
        float bb = __ldg(b2);
        float4 oo;
        oo.x = 1.0f / (1.0f + __expf(-(p0 + bb)));
        oo.y = 1.0f / (1.0f + __expf(-(p1 + bb)));
        oo.z = 1.0f / (1.0f + __expf(-(p2 + bb)));
        oo.w = 1.0f / (1.0f + __expf(-(p3 + bb)));
        *(float4*)(out + base) = oo;   // base % 4 == 0 -> 16B aligned
    }
}

// ---------------------------------------------------------------------------
extern "C" void kernel_launch(void* const* d_in, const int* in_sizes, int n_in,
                              void* d_out, int out_size)
{
    const float* x          = (const float*)d_in[0];
    const int*   edge_index = (const int*)d_in[1];
    const float* W1         = (const float*)d_in[2];
    const float* b1         = (const float*)d_in[3];
    const float* W2         = (const float*)d_in[4];
    const float* b2         = (const float*)d_in[5];
    float*       out        = (float*)d_out;

    const int n = in_sizes[0] / NODE_DIM;   // 100000
    const int E = in_sizes[1] / 2;          // 625000
    const int tiles = (n + 127) / 128;      // 782

    cudaFuncSetAttribute(node_gemm_persistent,
                         cudaFuncAttributeMaxDynamicSharedMemorySize,
                         (int)GEMM_SMEM);

    node_gemm_persistent<<<148, 256, GEMM_SMEM>>>(x, W1, b1, n, tiles);

    const int warps_needed = (E + 15) / 16;   // 39063
    const int threads = 256;
    const int edge_blocks = (warps_needed + (threads / 32) - 1) / (threads / 32);  // 4883
    edge_kernel<<<edge_blocks, threads>>>(edge_index, W2, b2, out, E);
}